// round 3
// baseline (speedup 1.0000x reference)
#include <cuda_runtime.h>
#include <cuda_bf16.h>
#include <mma.h>
#include <cstdint>

using namespace nvcuda;

// Problem constants
#define NN 50000
#define EE 640000
#define DN 128
#define DA 64
#define SS 128
#define HID 512
#define MAX_IT 10
#define THR2 1e-4f
#define NPAD 50048   // 391 * 128

// ---------------- device buffers ----------------
__device__ float d_SB[(size_t)NPAD * 256];       // [state | agg_states]
__device__ float d_stateold[(size_t)NPAD * 128];
__device__ float d_Abase[(size_t)NPAD * 320];    // [nodes | agg_nodes | agg_arcs]
__device__ float d_Bbase[(size_t)NPAD * 512];
__device__ float d_H[(size_t)NPAD * 512];
__device__ float d_NS[(size_t)NPAD * 128];
__device__ float d_SO[(size_t)NPAD * 256];       // [state | nodes]
__device__ float d_H2[(size_t)NPAD * 512];
__device__ float d_Wstack[256 * 512];
__device__ float d_Wbase[320 * 512];

__device__ int d_cnt_adj[NN];
__device__ int d_off_adj[NN + 1];
__device__ int d_cur_adj[NN];
__device__ int d_eid_adj[EE];
__device__ int d_cnt_an[NN];
__device__ int d_off_an[NN + 1];
__device__ int d_cur_an[NN];
__device__ int d_eid_an[EE];
__device__ int d_cont[MAX_IT + 1];

// ---------------- helpers ----------------
__device__ __forceinline__ float fast_tanh(float x) {
    float ax = fabsf(x);
    float e  = __expf(-2.0f * ax);
    float t  = __fdividef(1.0f - e, 1.0f + e);
    return copysignf(t, x);
}

// ---------------- setup ----------------
__global__ void setup_kernel() {
    int i = blockIdx.x * blockDim.x + threadIdx.x;
    if (i < NN) d_cnt_adj[i] = 0;
    else if (i < 2 * NN) d_cnt_an[i - NN] = 0;
    if (i <= MAX_IT) d_cont[i] = (i == 0) ? 1 : 0;
}

__global__ void count_kernel(const int* __restrict__ adj_dst, const int* __restrict__ an_dst) {
    int e = blockIdx.x * blockDim.x + threadIdx.x;
    if (e >= EE) return;
    atomicAdd(&d_cnt_adj[adj_dst[e]], 1);
    atomicAdd(&d_cnt_an[an_dst[e]], 1);
}

__global__ void scan_kernel() {
    __shared__ int sh[1024];
    int which = blockIdx.x;
    int* cnt = which ? d_cnt_an : d_cnt_adj;
    int* off = which ? d_off_an : d_off_adj;
    int* cur = which ? d_cur_an : d_cur_adj;
    int t = threadIdx.x;
    const int CH = (NN + 1023) / 1024;
    int base = t * CH;
    int s = 0;
    for (int i = 0; i < CH; i++) {
        int idx = base + i;
        if (idx < NN) s += cnt[idx];
    }
    sh[t] = s;
    __syncthreads();
    for (int d = 1; d < 1024; d <<= 1) {
        int v = (t >= d) ? sh[t - d] : 0;
        __syncthreads();
        sh[t] += v;
        __syncthreads();
    }
    int excl = (t == 0) ? 0 : sh[t - 1];
    for (int i = 0; i < CH; i++) {
        int idx = base + i;
        if (idx < NN) {
            off[idx] = excl;
            cur[idx] = excl;
            excl += cnt[idx];
        }
    }
    if (t == 1023) off[NN] = sh[1023];
}

__global__ void scatter_kernel(const int* __restrict__ adj_dst, const int* __restrict__ an_dst) {
    int e = blockIdx.x * blockDim.x + threadIdx.x;
    if (e >= EE) return;
    int p = atomicAdd(&d_cur_adj[adj_dst[e]], 1);
    d_eid_adj[p] = e;
    int q = atomicAdd(&d_cur_an[an_dst[e]], 1);
    d_eid_an[q] = e;
}

__global__ void pack_nodes_kernel(const float* __restrict__ nodes,
                                  const float* __restrict__ state_init) {
    int idx = blockIdx.x * blockDim.x + threadIdx.x;
    if (idx >= NN * 128) return;
    int n = idx >> 7, c = idx & 127;
    float nd = nodes[idx];
    d_SB[(size_t)n * 256 + c]       = state_init[idx];
    d_stateold[idx]                 = 1.0f;
    d_Abase[(size_t)n * 320 + c]    = nd;
    d_SO[(size_t)n * 256 + 128 + c] = nd;
}

__global__ void pack_w_kernel(const float* __restrict__ Ws1) {
    int idx = blockIdx.x * blockDim.x + threadIdx.x;
    if (idx < 256 * 512) {
        int r = idx >> 9, c = idx & 511;
        int sr = (r < 128) ? r : (r + 128);           // state rows / agg_state rows
        d_Wstack[idx] = Ws1[sr * 512 + c];
    } else if (idx < 256 * 512 + 320 * 512) {
        int i2 = idx - 256 * 512;
        int r = i2 >> 9, c = i2 & 511;
        int sr = (r < 128) ? (r + 128) : (r + 256);   // nodes rows / [aggn|agga] rows
        d_Wbase[i2] = Ws1[sr * 512 + c];
    }
}

// ---------------- aggregations ----------------
__global__ void agg_arcs_kernel(const float* __restrict__ arcs,
                                const float* __restrict__ an_vals) {
    int warp = (blockIdx.x * blockDim.x + threadIdx.x) >> 5;
    if (warp >= NN) return;
    int lane = threadIdx.x & 31;
    int p0 = d_off_an[warp], p1 = d_off_an[warp + 1];
    float a0 = 0.f, a1 = 0.f;
    for (int p = p0; p < p1; p++) {
        int e = d_eid_an[p];
        float v = an_vals[e];
        const float* ar = arcs + (size_t)e * 66;
        a0 += v * ar[2 + lane];
        a1 += v * ar[34 + lane];
    }
    d_Abase[(size_t)warp * 320 + 256 + lane] = a0;
    d_Abase[(size_t)warp * 320 + 288 + lane] = a1;
}

__global__ void spmm_kernel(const float* __restrict__ X, int xstr,
                            float* __restrict__ Y, int ystr,
                            const float* __restrict__ vals,
                            const int* __restrict__ src,
                            const int* __restrict__ gate) {
    if (gate && gate[0] == 0) return;
    int warp = (blockIdx.x * blockDim.x + threadIdx.x) >> 5;
    if (warp >= NN) return;
    int lane = threadIdx.x & 31;
    int p0 = d_off_adj[warp], p1 = d_off_adj[warp + 1];
    float a0 = 0.f, a1 = 0.f, a2 = 0.f, a3 = 0.f;
    for (int p = p0; p < p1; p++) {
        int e = d_eid_adj[p];
        float v = vals[e];
        const float* row = X + (size_t)src[e] * xstr;
        a0 += v * row[lane];
        a1 += v * row[lane + 32];
        a2 += v * row[lane + 64];
        a3 += v * row[lane + 96];
    }
    float* o = Y + (size_t)warp * ystr;
    o[lane] = a0; o[lane + 32] = a1; o[lane + 64] = a2; o[lane + 96] = a3;
}

// ---------------- convergence check ----------------
__global__ void conv_kernel(int it) {
    if (d_cont[it - 1] == 0) return;
    int warp = (blockIdx.x * blockDim.x + threadIdx.x) >> 5;
    if (warp >= NN) return;
    int lane = threadIdx.x & 31;
    float d2 = 0.f, n2 = 0.f;
#pragma unroll
    for (int j = 0; j < 4; j++) {
        float s  = d_SB[(size_t)warp * 256 + lane + 32 * j];
        float so = d_stateold[(size_t)warp * 128 + lane + 32 * j];
        float df = s - so;
        d2 += df * df;
        n2 += so * so;
    }
#pragma unroll
    for (int o = 16; o; o >>= 1) {
        d2 += __shfl_down_sync(0xffffffffu, d2, o);
        n2 += __shfl_down_sync(0xffffffffu, n2, o);
    }
    if (lane == 0 && d2 > THR2 * n2) d_cont[it] = 1;
}

__global__ void update_kernel(const int* __restrict__ gate) {
    if (gate[0] == 0) return;
    int idx = blockIdx.x * blockDim.x + threadIdx.x;
    if (idx >= NN * 128) return;
    int n = idx >> 7, c = idx & 127;
    float old = d_SB[(size_t)n * 256 + c];
    d_stateold[idx] = old;
    d_SB[(size_t)n * 256 + c] = d_NS[idx];
}

__global__ void copy_so_kernel() {
    int idx = blockIdx.x * blockDim.x + threadIdx.x;
    if (idx >= NN * 128) return;
    int n = idx >> 7, c = idx & 127;
    d_SO[(size_t)n * 256 + c] = d_SB[(size_t)n * 256 + c];
}

// ---------------- TF32 WMMA GEMM ----------------
// C[M x Ncols] = act( A[M x K] @ B[K x Ncols] + init ),  M covered by grid (padded),
// IM==0: init = bias vector Ci[Ncols];  IM==1: init = full matrix Ci (ldci)
// ACT==1: tanh
#define BM 128
#define BN 64
#define BK 32

template <int IM, int ACTF>
__global__ __launch_bounds__(256) void gemm_tf32(
    const float* __restrict__ A, int lda,
    const float* __restrict__ B, int ldb,
    const float* __restrict__ Ci, int ldci,
    float* __restrict__ C, int ldc,
    int K, const int* __restrict__ gate)
{
    if (gate && gate[0] == 0) return;
    __shared__ float As[BM][BK];
    __shared__ float Bs[BK][BN + 4];
    __shared__ float biasS[16][BN];

    int m0 = blockIdx.x * BM;
    int n0 = blockIdx.y * BN;
    int tid = threadIdx.x;
    int wid = tid >> 5;
    int wm = wid >> 1, wn = wid & 1;

    if (IM == 0) {
        for (int i = tid; i < 16 * BN; i += 256)
            biasS[i / BN][i % BN] = Ci[n0 + (i % BN)];
    }
    __syncthreads();

    wmma::fragment<wmma::accumulator, 16, 16, 8, float> acc[2][2];
#pragma unroll
    for (int i = 0; i < 2; i++)
#pragma unroll
        for (int j = 0; j < 2; j++) {
            if (IM == 0) {
                wmma::load_matrix_sync(acc[i][j], &biasS[0][wn * 32 + j * 16], BN,
                                       wmma::mem_row_major);
            } else {
                wmma::load_matrix_sync(acc[i][j],
                    Ci + (size_t)(m0 + wm * 32 + i * 16) * ldci + n0 + wn * 32 + j * 16,
                    ldci, wmma::mem_row_major);
            }
        }

    for (int k0 = 0; k0 < K; k0 += BK) {
        __syncthreads();
        const float* Ag = A + (size_t)m0 * lda + k0;
#pragma unroll
        for (int i = 0; i < 4; i++) {
            int idx = tid + i * 256;          // 0..1023, 128 rows x 8 float4
            int r = idx >> 3, cv = (idx & 7) * 4;
            *(float4*)&As[r][cv] = *(const float4*)&Ag[(size_t)r * lda + cv];
        }
        const float* Bg = B + (size_t)k0 * ldb + n0;
#pragma unroll
        for (int i = 0; i < 2; i++) {
            int idx = tid + i * 256;          // 0..511, 32 rows x 16 float4
            int r = idx >> 4, cv = (idx & 15) * 4;
            *(float4*)&Bs[r][cv] = *(const float4*)&Bg[(size_t)r * ldb + cv];
        }
        __syncthreads();
#pragma unroll
        for (int kk = 0; kk < BK; kk += 8) {
            wmma::fragment<wmma::matrix_a, 16, 16, 8, wmma::precision::tf32, wmma::row_major> af[2];
            wmma::fragment<wmma::matrix_b, 16, 16, 8, wmma::precision::tf32, wmma::row_major> bf[2];
#pragma unroll
            for (int i = 0; i < 2; i++) {
                wmma::load_matrix_sync(af[i], &As[wm * 32 + i * 16][kk], BK);
#pragma unroll
                for (int e = 0; e < af[i].num_elements; e++)
                    af[i].x[e] = wmma::__float_to_tf32(af[i].x[e]);
            }
#pragma unroll
            for (int j = 0; j < 2; j++) {
                wmma::load_matrix_sync(bf[j], &Bs[kk][wn * 32 + j * 16], BN + 4);
#pragma unroll
                for (int e = 0; e < bf[j].num_elements; e++)
                    bf[j].x[e] = wmma::__float_to_tf32(bf[j].x[e]);
            }
#pragma unroll
            for (int i = 0; i < 2; i++)
#pragma unroll
                for (int j = 0; j < 2; j++)
                    wmma::mma_sync(acc[i][j], af[i], bf[j], acc[i][j]);
        }
    }

#pragma unroll
    for (int i = 0; i < 2; i++)
#pragma unroll
        for (int j = 0; j < 2; j++) {
            if (ACTF == 1) {
#pragma unroll
                for (int e = 0; e < acc[i][j].num_elements; e++)
                    acc[i][j].x[e] = fast_tanh(acc[i][j].x[e]);
            }
            wmma::store_matrix_sync(
                C + (size_t)(m0 + wm * 32 + i * 16) * ldc + n0 + wn * 32 + j * 16,
                acc[i][j], ldc, wmma::mem_row_major);
        }
}

// ---------------- output head ----------------
__global__ void out_kernel(const float* __restrict__ Wo2, const float* __restrict__ bo2,
                           const int* __restrict__ sm, const int* __restrict__ om,
                           float* __restrict__ out) {
    __shared__ float w[512 * 7];
    __shared__ float b[7];
    for (int i = threadIdx.x; i < 512 * 7; i += blockDim.x) w[i] = Wo2[i];
    if (threadIdx.x < 7) b[threadIdx.x] = bo2[threadIdx.x];
    __syncthreads();
    int warp = (blockIdx.x * blockDim.x + threadIdx.x) >> 5;
    if (warp >= NN) return;
    int lane = threadIdx.x & 31;
    float acc[7] = {0, 0, 0, 0, 0, 0, 0};
    const float* h = d_H2 + (size_t)warp * 512;
    for (int k = lane; k < 512; k += 32) {
        float hv = h[k];
#pragma unroll
        for (int j = 0; j < 7; j++) acc[j] += hv * w[k * 7 + j];
    }
#pragma unroll
    for (int j = 0; j < 7; j++)
#pragma unroll
        for (int o = 16; o; o >>= 1)
            acc[j] += __shfl_down_sync(0xffffffffu, acc[j], o);
    if (lane == 0) {
        float m = (sm[warp] != 0 && om[warp] != 0) ? 1.0f : 0.0f;
#pragma unroll
        for (int j = 0; j < 7; j++) out[(size_t)warp * 7 + j] = (acc[j] + b[j]) * m;
    }
}

// ---------------- host launch ----------------
extern "C" void kernel_launch(void* const* d_in, const int* in_sizes, int n_in,
                              void* d_out, int out_size) {
    const float* nodes      = (const float*)d_in[0];
    const float* arcs       = (const float*)d_in[1];
    const int* set_mask     = (const int*)d_in[2];     // bool stored as int32
    const int* out_mask     = (const int*)d_in[3];     // bool stored as int32
    const int* adj_src      = (const int*)d_in[4];
    const int* adj_dst      = (const int*)d_in[5];
    const float* adj_vals   = (const float*)d_in[6];
    const int* an_dst       = (const int*)d_in[7];
    const float* an_vals    = (const float*)d_in[8];
    const float* state_init = (const float*)d_in[9];
    const float* Ws1        = (const float*)d_in[10];
    const float* bs1        = (const float*)d_in[11];
    const float* Ws2        = (const float*)d_in[12];
    const float* bs2        = (const float*)d_in[13];
    const float* Wo1        = (const float*)d_in[14];
    const float* bo1        = (const float*)d_in[15];
    const float* Wo2        = (const float*)d_in[16];
    const float* bo2        = (const float*)d_in[17];
    float* out              = (float*)d_out;

    // device symbol addresses
    float *pSB, *pSO, *pAbase, *pBbase, *pH, *pNS, *pH2, *pWstack, *pWbase;
    int* pcont;
    cudaGetSymbolAddress((void**)&pSB, d_SB);
    cudaGetSymbolAddress((void**)&pSO, d_SO);
    cudaGetSymbolAddress((void**)&pAbase, d_Abase);
    cudaGetSymbolAddress((void**)&pBbase, d_Bbase);
    cudaGetSymbolAddress((void**)&pH, d_H);
    cudaGetSymbolAddress((void**)&pNS, d_NS);
    cudaGetSymbolAddress((void**)&pH2, d_H2);
    cudaGetSymbolAddress((void**)&pWstack, d_Wstack);
    cudaGetSymbolAddress((void**)&pWbase, d_Wbase);
    cudaGetSymbolAddress((void**)&pcont, d_cont);

    const int T = 256;
    // setup + CSR build
    setup_kernel<<<(2 * NN + T - 1) / T, T>>>();
    count_kernel<<<(EE + T - 1) / T, T>>>(adj_dst, an_dst);
    scan_kernel<<<2, 1024>>>();
    scatter_kernel<<<(EE + T - 1) / T, T>>>(adj_dst, an_dst);

    pack_nodes_kernel<<<(NN * 128 + T - 1) / T, T>>>(nodes, state_init);
    pack_w_kernel<<<(256 * 512 + 320 * 512 + T - 1) / T, T>>>(Ws1);

    int warpBlocks = (NN * 32 + T - 1) / T;
    agg_arcs_kernel<<<warpBlocks, T>>>(arcs, an_vals);
    // agg_nodes -> Abase cols 128:256
    spmm_kernel<<<warpBlocks, T>>>(nodes, 128, pAbase + 128, 320, adj_vals, adj_src, nullptr);

    // Bbase = Abase @ Wbase + bs1  (no act)
    dim3 gB(NPAD / BM, 512 / BN);
    gemm_tf32<0, 0><<<gB, 256>>>(pAbase, 320, pWbase, 512, bs1, 0, pBbase, 512, 320, nullptr);

    for (int it = 1; it <= MAX_IT; it++) {
        conv_kernel<<<warpBlocks, T>>>(it);
        // agg_states -> SB cols 128:256
        spmm_kernel<<<warpBlocks, T>>>(pSB, 256, pSB + 128, 256, adj_vals, adj_src, pcont + it);
        // H = tanh(SB @ Wstack + Bbase)
        gemm_tf32<1, 1><<<dim3(NPAD / BM, 512 / BN), 256>>>(
            pSB, 256, pWstack, 512, pBbase, 512, pH, 512, 256, pcont + it);
        // NS = tanh(H @ Ws2 + bs2)
        gemm_tf32<0, 1><<<dim3(NPAD / BM, 128 / BN), 256>>>(
            pH, 512, Ws2, 128, bs2, 0, pNS, 128, 512, pcont + it);
        update_kernel<<<(NN * 128 + T - 1) / T, T>>>(pcont + it);
    }

    copy_so_kernel<<<(NN * 128 + T - 1) / T, T>>>();
    // H2 = tanh(SO @ Wo1 + bo1)
    gemm_tf32<0, 1><<<dim3(NPAD / BM, 512 / BN), 256>>>(
        pSO, 256, Wo1, 512, bo1, 0, pH2, 512, 256, nullptr);
    out_kernel<<<warpBlocks, T>>>(Wo2, bo2, set_mask, out_mask, out);
}

// round 5
// speedup vs baseline: 1.1559x; 1.1559x over previous
#include <cuda_runtime.h>
#include <cuda_bf16.h>
#include <mma.h>
#include <cstdint>

using namespace nvcuda;

// Problem constants
#define NN 50000
#define EE 640000
#define MAX_IT 10
#define THR2 1e-4f
#define NPAD 50048   // 391 * 128

// ---------------- device buffers ----------------
__device__ float d_SB[(size_t)NPAD * 256];       // [state | agg_states]
__device__ float d_stateold[(size_t)NPAD * 128];
__device__ float d_Abase[(size_t)NPAD * 320];    // [nodes | agg_nodes | agg_arcs]
__device__ float d_Bbase[(size_t)NPAD * 512];
__device__ float d_H[(size_t)NPAD * 512];
__device__ float d_NS[(size_t)NPAD * 128];
__device__ float d_SO[(size_t)NPAD * 256];       // [state | nodes]
__device__ float d_H2[(size_t)NPAD * 512];
__device__ float d_Wstack[256 * 512];
__device__ float d_Wbase[320 * 512];

__device__ int d_cnt_adj[NN];
__device__ int d_off_adj[NN + 1];
__device__ int d_cur_adj[NN];
__device__ int d_eid_adj[EE];
__device__ int d_cnt_an[NN];
__device__ int d_off_an[NN + 1];
__device__ int d_cur_an[NN];
__device__ int d_eid_an[EE];
__device__ int d_cont[MAX_IT + 2];

// ---------------- helpers ----------------
__device__ __forceinline__ float fast_tanh(float x) {
    float ax = fabsf(x);
    float e  = __expf(-2.0f * ax);
    float t  = __fdividef(1.0f - e, 1.0f + e);
    return copysignf(t, x);
}

__device__ __forceinline__ void cpa16(float* dst, const float* src) {
    unsigned d = (unsigned)__cvta_generic_to_shared(dst);
    asm volatile("cp.async.cg.shared.global [%0], [%1], 16;" :: "r"(d), "l"(src));
}
#define CP_COMMIT asm volatile("cp.async.commit_group;")
#define CP_WAIT0  asm volatile("cp.async.wait_group 0;")
#define CP_WAIT1  asm volatile("cp.async.wait_group 1;")

// ---------------- setup ----------------
__global__ void setup_kernel() {
    int i = blockIdx.x * blockDim.x + threadIdx.x;
    if (i < NN) d_cnt_adj[i] = 0;
    else if (i < 2 * NN) d_cnt_an[i - NN] = 0;
    if (i <= MAX_IT + 1) d_cont[i] = (i == 0) ? 1 : 0;
}

__global__ void count_kernel(const int* __restrict__ adj_dst, const int* __restrict__ an_dst) {
    int e = blockIdx.x * blockDim.x + threadIdx.x;
    if (e >= EE) return;
    atomicAdd(&d_cnt_adj[adj_dst[e]], 1);
    atomicAdd(&d_cnt_an[an_dst[e]], 1);
}

__global__ void scan_kernel() {
    __shared__ int sh[1024];
    int which = blockIdx.x;
    int* cnt = which ? d_cnt_an : d_cnt_adj;
    int* off = which ? d_off_an : d_off_adj;
    int* cur = which ? d_cur_an : d_cur_adj;
    int t = threadIdx.x;
    const int CH = (NN + 1023) / 1024;
    int base = t * CH;
    int s = 0;
    for (int i = 0; i < CH; i++) {
        int idx = base + i;
        if (idx < NN) s += cnt[idx];
    }
    sh[t] = s;
    __syncthreads();
    for (int d = 1; d < 1024; d <<= 1) {
        int v = (t >= d) ? sh[t - d] : 0;
        __syncthreads();
        sh[t] += v;
        __syncthreads();
    }
    int excl = (t == 0) ? 0 : sh[t - 1];
    for (int i = 0; i < CH; i++) {
        int idx = base + i;
        if (idx < NN) {
            off[idx] = excl;
            cur[idx] = excl;
            excl += cnt[idx];
        }
    }
    if (t == 1023) off[NN] = sh[1023];
}

__global__ void scatter_kernel(const int* __restrict__ adj_dst, const int* __restrict__ an_dst) {
    int e = blockIdx.x * blockDim.x + threadIdx.x;
    if (e >= EE) return;
    int p = atomicAdd(&d_cur_adj[adj_dst[e]], 1);
    d_eid_adj[p] = e;
    int q = atomicAdd(&d_cur_an[an_dst[e]], 1);
    d_eid_an[q] = e;
}

__global__ void pack_nodes_kernel(const float* __restrict__ nodes,
                                  const float* __restrict__ state_init) {
    int idx = blockIdx.x * blockDim.x + threadIdx.x;
    if (idx >= NN * 128) return;
    int n = idx >> 7, c = idx & 127;
    float nd = nodes[idx];
    d_SB[(size_t)n * 256 + c]       = state_init[idx];
    d_stateold[idx]                 = 1.0f;
    d_Abase[(size_t)n * 320 + c]    = nd;
    d_SO[(size_t)n * 256 + 128 + c] = nd;
}

__global__ void pack_w_kernel(const float* __restrict__ Ws1) {
    int idx = blockIdx.x * blockDim.x + threadIdx.x;
    if (idx < 256 * 512) {
        int r = idx >> 9, c = idx & 511;
        int sr = (r < 128) ? r : (r + 128);           // state rows / agg_state rows
        d_Wstack[idx] = Ws1[sr * 512 + c];
    } else if (idx < 256 * 512 + 320 * 512) {
        int i2 = idx - 256 * 512;
        int r = i2 >> 9, c = i2 & 511;
        int sr = (r < 128) ? (r + 128) : (r + 256);   // nodes rows / [aggn|agga] rows
        d_Wbase[i2] = Ws1[sr * 512 + c];
    }
}

// ---------------- aggregations ----------------
__global__ void agg_arcs_kernel(const float* __restrict__ arcs,
                                const float* __restrict__ an_vals) {
    int warp = (blockIdx.x * blockDim.x + threadIdx.x) >> 5;
    if (warp >= NN) return;
    int lane = threadIdx.x & 31;
    int p0 = d_off_an[warp], p1 = d_off_an[warp + 1];
    float a0 = 0.f, a1 = 0.f;
    for (int p = p0; p < p1; p++) {
        int e = d_eid_an[p];
        float v = an_vals[e];
        const float* ar = arcs + (size_t)e * 66;
        a0 += v * ar[2 + lane];
        a1 += v * ar[34 + lane];
    }
    d_Abase[(size_t)warp * 320 + 256 + lane] = a0;
    d_Abase[(size_t)warp * 320 + 288 + lane] = a1;
}

// gather SpMM: one warp per destination node; one float4 per lane per source row
__global__ void spmm_kernel(const float4* __restrict__ X4, int xstr4,
                            float4* __restrict__ Y4, int ystr4,
                            const float* __restrict__ vals,
                            const int* __restrict__ src,
                            const int* __restrict__ gate) {
    if (gate && gate[0] == 0) return;
    int warp = (blockIdx.x * blockDim.x + threadIdx.x) >> 5;
    if (warp >= NN) return;
    int lane = threadIdx.x & 31;
    int p0 = d_off_adj[warp], p1 = d_off_adj[warp + 1];
    float4 a = make_float4(0.f, 0.f, 0.f, 0.f);
    for (int p = p0; p < p1; p++) {
        int e = d_eid_adj[p];
        float v = vals[e];
        float4 r = X4[(size_t)src[e] * xstr4 + lane];
        a.x += v * r.x; a.y += v * r.y; a.z += v * r.z; a.w += v * r.w;
    }
    Y4[(size_t)warp * ystr4 + lane] = a;
}

// ---------------- initial convergence check (it=1) ----------------
__global__ void conv_kernel(int it) {
    if (d_cont[it - 1] == 0) return;
    int warp = (blockIdx.x * blockDim.x + threadIdx.x) >> 5;
    if (warp >= NN) return;
    int lane = threadIdx.x & 31;
    float d2 = 0.f, n2 = 0.f;
#pragma unroll
    for (int j = 0; j < 4; j++) {
        float s  = d_SB[(size_t)warp * 256 + lane + 32 * j];
        float so = d_stateold[(size_t)warp * 128 + lane + 32 * j];
        float df = s - so;
        d2 += df * df;
        n2 += so * so;
    }
#pragma unroll
    for (int o = 16; o; o >>= 1) {
        d2 += __shfl_down_sync(0xffffffffu, d2, o);
        n2 += __shfl_down_sync(0xffffffffu, n2, o);
    }
    if (lane == 0 && d2 > THR2 * n2) d_cont[it] = 1;
}

// ---------------- fused state update + next-iteration convergence ----------------
__global__ void update_conv_kernel(int it) {
    if (d_cont[it] == 0) return;
    int warp = (blockIdx.x * blockDim.x + threadIdx.x) >> 5;
    if (warp >= NN) return;
    int lane = threadIdx.x & 31;
    const float4* ns4 = (const float4*)d_NS;
    float4* sb4 = (float4*)d_SB;
    float4* so4 = (float4*)d_stateold;
    float4 nv = ns4[(size_t)warp * 32 + lane];
    float4 ov = sb4[(size_t)warp * 64 + lane];
    so4[(size_t)warp * 32 + lane] = ov;
    sb4[(size_t)warp * 64 + lane] = nv;
    float dx = nv.x - ov.x, dy = nv.y - ov.y, dz = nv.z - ov.z, dw = nv.w - ov.w;
    float d2 = dx * dx + dy * dy + dz * dz + dw * dw;
    float n2 = ov.x * ov.x + ov.y * ov.y + ov.z * ov.z + ov.w * ov.w;
#pragma unroll
    for (int o = 16; o; o >>= 1) {
        d2 += __shfl_xor_sync(0xffffffffu, d2, o);
        n2 += __shfl_xor_sync(0xffffffffu, n2, o);
    }
    if (lane == 0 && d2 > THR2 * n2) d_cont[it + 1] = 1;
}

__global__ void copy_so_kernel() {
    int idx = blockIdx.x * blockDim.x + threadIdx.x;
    if (idx >= NN * 32) return;
    int n = idx >> 5, c = idx & 31;
    ((float4*)d_SO)[(size_t)n * 64 + c] = ((const float4*)d_SB)[(size_t)n * 64 + c];
}

// ---------------- TF32 WMMA GEMM, cp.async double-buffered ----------------
// C[M x N] = act( A[M x K] @ B[K x N] + Ci ),  Ci with ldci (ldci==0 => bias broadcast)
#define BMg 128
#define BNg 128
#define BKg 16
#define GT  512

template <int ACTF>
__global__ __launch_bounds__(GT) void gemm_tf32(
    const float* __restrict__ A, int lda,
    const float* __restrict__ B, int ldb,
    const float* __restrict__ Ci, int ldci,
    float* __restrict__ C, int ldc,
    int K, const int* __restrict__ gate)
{
    if (gate && gate[0] == 0) return;
    __shared__ float As[2][BMg][BKg + 8];   // row stride 24 floats (96B, 16B-aligned)
    __shared__ float Bs[2][BKg][BNg + 8];   // row stride 136 floats (544B, 16B-aligned)

    int tid = threadIdx.x;
    int wid = tid >> 5;
    int wm = wid & 3;        // 4 m-tiles of 32 rows
    int wn = wid >> 2;       // 4 n-tiles of 32 cols
    int m0 = blockIdx.x * BMg;
    int n0 = blockIdx.y * BNg;

    // init accumulators from Ci (matrix if ldci>0, broadcast bias if ldci==0)
    wmma::fragment<wmma::accumulator, 16, 16, 8, float> acc[2][2];
#pragma unroll
    for (int i = 0; i < 2; i++)
#pragma unroll
        for (int j = 0; j < 2; j++)
            wmma::load_matrix_sync(acc[i][j],
                Ci + (size_t)(m0 + wm * 32 + i * 16) * ldci + n0 + wn * 32 + j * 16,
                ldci, wmma::mem_row_major);

    // per-thread load coordinates (512 threads: 1 float4 each for A and B per stage)
    int ar = tid >> 2, ac = (tid & 3) * 4;     // A: 128 rows x 4 float4
    int br = tid >> 5, bc = (tid & 31) * 4;    // B: 16 rows x 32 float4
    const float* Ab = A + (size_t)m0 * lda;
    const float* Bb = B + n0;

    // prologue: stage 0
    cpa16(&As[0][ar][ac], Ab + (size_t)ar * lda + ac);
    cpa16(&Bs[0][br][bc], Bb + (size_t)br * ldb + bc);
    CP_COMMIT;

    int nst = K / BKg;
    for (int s = 0; s < nst; s++) {
        int cur = s & 1;
        if (s + 1 < nst) {
            int nxt = cur ^ 1;
            int k0 = (s + 1) * BKg;
            cpa16(&As[nxt][ar][ac], Ab + (size_t)ar * lda + k0 + ac);
            cpa16(&Bs[nxt][br][bc], Bb + (size_t)(k0 + br) * ldb + bc);
            CP_COMMIT;
            CP_WAIT1;
        } else {
            CP_WAIT0;
        }
        __syncthreads();
#pragma unroll
        for (int kk = 0; kk < BKg; kk += 8) {
            wmma::fragment<wmma::matrix_a, 16, 16, 8, wmma::precision::tf32, wmma::row_major> af[2];
            wmma::fragment<wmma::matrix_b, 16, 16, 8, wmma::precision::tf32, wmma::row_major> bf[2];
#pragma unroll
            for (int i = 0; i < 2; i++) {
                wmma::load_matrix_sync(af[i], &As[cur][wm * 32 + i * 16][kk], BKg + 8);
#pragma unroll
                for (int e = 0; e < af[i].num_elements; e++)
                    af[i].x[e] = wmma::__float_to_tf32(af[i].x[e]);
            }
#pragma unroll
            for (int j = 0; j < 2; j++) {
                wmma::load_matrix_sync(bf[j], &Bs[cur][kk][wn * 32 + j * 16], BNg + 8);
#pragma unroll
                for (int e = 0; e < bf[j].num_elements; e++)
                    bf[j].x[e] = wmma::__float_to_tf32(bf[j].x[e]);
            }
#pragma unroll
            for (int i = 0; i < 2; i++)
#pragma unroll
                for (int j = 0; j < 2; j++)
                    wmma::mma_sync(acc[i][j], af[i], bf[j], acc[i][j]);
        }
        __syncthreads();
    }

#pragma unroll
    for (int i = 0; i < 2; i++)
#pragma unroll
        for (int j = 0; j < 2; j++) {
            if (ACTF == 1) {
#pragma unroll
                for (int e = 0; e < acc[i][j].num_elements; e++)
                    acc[i][j].x[e] = fast_tanh(acc[i][j].x[e]);
            }
            wmma::store_matrix_sync(
                C + (size_t)(m0 + wm * 32 + i * 16) * ldc + n0 + wn * 32 + j * 16,
                acc[i][j], ldc, wmma::mem_row_major);
        }
}

// ---------------- output head ----------------
__global__ void out_kernel(const float* __restrict__ Wo2, const float* __restrict__ bo2,
                           const int* __restrict__ sm, const int* __restrict__ om,
                           float* __restrict__ out) {
    __shared__ float w[512 * 7];
    __shared__ float b[7];
    for (int i = threadIdx.x; i < 512 * 7; i += blockDim.x) w[i] = Wo2[i];
    if (threadIdx.x < 7) b[threadIdx.x] = bo2[threadIdx.x];
    __syncthreads();
    int warp = (blockIdx.x * blockDim.x + threadIdx.x) >> 5;
    if (warp >= NN) return;
    int lane = threadIdx.x & 31;
    float acc[7] = {0, 0, 0, 0, 0, 0, 0};
    const float* h = d_H2 + (size_t)warp * 512;
    for (int k = lane; k < 512; k += 32) {
        float hv = h[k];
#pragma unroll
        for (int j = 0; j < 7; j++) acc[j] += hv * w[k * 7 + j];
    }
#pragma unroll
    for (int j = 0; j < 7; j++)
#pragma unroll
        for (int o = 16; o; o >>= 1)
            acc[j] += __shfl_down_sync(0xffffffffu, acc[j], o);
    if (lane == 0) {
        float m = (sm[warp] != 0 && om[warp] != 0) ? 1.0f : 0.0f;
#pragma unroll
        for (int j = 0; j < 7; j++) out[(size_t)warp * 7 + j] = (acc[j] + b[j]) * m;
    }
}

// ---------------- host launch ----------------
extern "C" void kernel_launch(void* const* d_in, const int* in_sizes, int n_in,
                              void* d_out, int out_size) {
    const float* nodes      = (const float*)d_in[0];
    const float* arcs       = (const float*)d_in[1];
    const int* set_mask     = (const int*)d_in[2];     // bool stored as int32
    const int* out_mask     = (const int*)d_in[3];
    const int* adj_src      = (const int*)d_in[4];
    const int* adj_dst      = (const int*)d_in[5];
    const float* adj_vals   = (const float*)d_in[6];
    const int* an_dst       = (const int*)d_in[7];
    const float* an_vals    = (const float*)d_in[8];
    const float* state_init = (const float*)d_in[9];
    const float* Ws1        = (const float*)d_in[10];
    const float* bs1        = (const float*)d_in[11];
    const float* Ws2        = (const float*)d_in[12];
    const float* bs2        = (const float*)d_in[13];
    const float* Wo1        = (const float*)d_in[14];
    const float* bo1        = (const float*)d_in[15];
    const float* Wo2        = (const float*)d_in[16];
    const float* bo2        = (const float*)d_in[17];
    float* out              = (float*)d_out;

    float *pSB, *pSO, *pAbase, *pBbase, *pH, *pNS, *pH2, *pWstack, *pWbase;
    int* pcont;
    cudaGetSymbolAddress((void**)&pSB, d_SB);
    cudaGetSymbolAddress((void**)&pSO, d_SO);
    cudaGetSymbolAddress((void**)&pAbase, d_Abase);
    cudaGetSymbolAddress((void**)&pBbase, d_Bbase);
    cudaGetSymbolAddress((void**)&pH, d_H);
    cudaGetSymbolAddress((void**)&pNS, d_NS);
    cudaGetSymbolAddress((void**)&pH2, d_H2);
    cudaGetSymbolAddress((void**)&pWstack, d_Wstack);
    cudaGetSymbolAddress((void**)&pWbase, d_Wbase);
    cudaGetSymbolAddress((void**)&pcont, d_cont);

    const int T = 256;
    // setup + CSR build
    setup_kernel<<<(2 * NN + T - 1) / T, T>>>();
    count_kernel<<<(EE + T - 1) / T, T>>>(adj_dst, an_dst);
    scan_kernel<<<2, 1024>>>();
    scatter_kernel<<<(EE + T - 1) / T, T>>>(adj_dst, an_dst);

    pack_nodes_kernel<<<(NN * 128 + T - 1) / T, T>>>(nodes, state_init);
    pack_w_kernel<<<(256 * 512 + 320 * 512 + T - 1) / T, T>>>(Ws1);

    int warpBlocks = (NN * 32 + T - 1) / T;
    agg_arcs_kernel<<<warpBlocks, T>>>(arcs, an_vals);
    // agg_nodes -> Abase cols 128:256   (nodes row = 32 float4, Abase row = 80 float4)
    spmm_kernel<<<warpBlocks, T>>>((const float4*)nodes, 32,
                                   ((float4*)pAbase) + 32, 80, adj_vals, adj_src, nullptr);

    // Bbase = Abase @ Wbase + bs1  (no act)
    gemm_tf32<0><<<dim3(NPAD / BMg, 512 / BNg), GT>>>(
        pAbase, 320, pWbase, 512, bs1, 0, pBbase, 512, 320, nullptr);

    conv_kernel<<<warpBlocks, T>>>(1);

    for (int it = 1; it <= MAX_IT; it++) {
        // agg_states -> SB cols 128:256  (SB row = 64 float4)
        spmm_kernel<<<warpBlocks, T>>>((const float4*)pSB, 64,
                                       ((float4*)pSB) + 32, 64, adj_vals, adj_src, pcont + it);
        // H = tanh(SB @ Wstack + Bbase)
        gemm_tf32<1><<<dim3(NPAD / BMg, 512 / BNg), GT>>>(
            pSB, 256, pWstack, 512, pBbase, 512, pH, 512, 256, pcont + it);
        // NS = tanh(H @ Ws2 + bs2)
        gemm_tf32<1><<<dim3(NPAD / BMg, 128 / BNg), GT>>>(
            pH, 512, Ws2, 128, bs2, 0, pNS, 128, 512, pcont + it);
        // state <- NS, stateold <- state, cont[it+1] from (new,old)
        update_conv_kernel<<<warpBlocks, T>>>(it);
    }

    copy_so_kernel<<<(NN * 32 + T - 1) / T, T>>>();
    // H2 = tanh(SO @ Wo1 + bo1)
    gemm_tf32<1><<<dim3(NPAD / BMg, 512 / BNg), GT>>>(
        pSO, 256, Wo1, 512, bo1, 0, pH2, 512, 256, nullptr);
    out_kernel<<<warpBlocks, T>>>(Wo2, bo2, set_mask, out_mask, out);
}

// round 14
// speedup vs baseline: 1.3806x; 1.1945x over previous
#include <cuda_runtime.h>
#include <cuda_bf16.h>
#include <mma.h>
#include <cstdint>

using namespace nvcuda;

// Problem constants
#define NN 50000
#define EE 640000
#define MAX_IT 10
#define THR2 1e-4f
#define NPAD 50048   // 391 * 128

// ---------------- device buffers ----------------
__device__ float d_SB[(size_t)NPAD * 256];       // [state | agg_states]
__device__ float d_stateold[(size_t)NPAD * 128];
__device__ float d_Abase[(size_t)NPAD * 320];    // [nodes | agg_nodes | agg_arcs]
__device__ float d_Bbase[(size_t)NPAD * 512];
__device__ float d_H[(size_t)NPAD * 512];
__device__ float d_NS[(size_t)NPAD * 128];
__device__ float d_SO[(size_t)NPAD * 256];       // [state | nodes]
__device__ float d_H2[(size_t)NPAD * 512];
__device__ float d_Wstack[256 * 512];
__device__ float d_Wbase[320 * 512];

__device__ int d_cnt_adj[NN];
__device__ int d_off_adj[NN + 1];
__device__ int d_cur_adj[NN];
__device__ int d_eid_adj[EE];
__device__ int d_cnt_an[NN];
__device__ int d_off_an[NN + 1];
__device__ int d_cur_an[NN];
__device__ int d_eid_an[EE];
__device__ int d_cont[MAX_IT + 2];

// ---------------- helpers ----------------
__device__ __forceinline__ float fast_tanh(float x) {
    float ax = fabsf(x);
    float e  = __expf(-2.0f * ax);
    float t  = __fdividef(1.0f - e, 1.0f + e);
    return copysignf(t, x);
}

__device__ __forceinline__ void cpa16(float* dst, const float* src) {
    unsigned d = (unsigned)__cvta_generic_to_shared(dst);
    asm volatile("cp.async.cg.shared.global [%0], [%1], 16;" :: "r"(d), "l"(src));
}
#define CP_COMMIT asm volatile("cp.async.commit_group;")
#define CP_WAIT0  asm volatile("cp.async.wait_group 0;")
#define CP_WAIT1  asm volatile("cp.async.wait_group 1;")

// ---------------- setup ----------------
__global__ void setup_kernel() {
    int i = blockIdx.x * blockDim.x + threadIdx.x;
    if (i < NN) d_cnt_adj[i] = 0;
    else if (i < 2 * NN) d_cnt_an[i - NN] = 0;
    if (i <= MAX_IT + 1) d_cont[i] = (i == 0) ? 1 : 0;
}

__global__ void count_kernel(const int* __restrict__ adj_dst, const int* __restrict__ an_dst) {
    int e = blockIdx.x * blockDim.x + threadIdx.x;
    if (e >= EE) return;
    atomicAdd(&d_cnt_adj[adj_dst[e]], 1);
    atomicAdd(&d_cnt_an[an_dst[e]], 1);
}

__global__ void scan_kernel() {
    __shared__ int sh[1024];
    int which = blockIdx.x;
    int* cnt = which ? d_cnt_an : d_cnt_adj;
    int* off = which ? d_off_an : d_off_adj;
    int* cur = which ? d_cur_an : d_cur_adj;
    int t = threadIdx.x;
    const int CH = (NN + 1023) / 1024;
    int base = t * CH;
    int s = 0;
    for (int i = 0; i < CH; i++) {
        int idx = base + i;
        if (idx < NN) s += cnt[idx];
    }
    sh[t] = s;
    __syncthreads();
    for (int d = 1; d < 1024; d <<= 1) {
        int v = (t >= d) ? sh[t - d] : 0;
        __syncthreads();
        sh[t] += v;
        __syncthreads();
    }
    int excl = (t == 0) ? 0 : sh[t - 1];
    for (int i = 0; i < CH; i++) {
        int idx = base + i;
        if (idx < NN) {
            off[idx] = excl;
            cur[idx] = excl;
            excl += cnt[idx];
        }
    }
    if (t == 1023) off[NN] = sh[1023];
}

__global__ void scatter_kernel(const int* __restrict__ adj_dst, const int* __restrict__ an_dst) {
    int e = blockIdx.x * blockDim.x + threadIdx.x;
    if (e >= EE) return;
    int p = atomicAdd(&d_cur_adj[adj_dst[e]], 1);
    d_eid_adj[p] = e;
    int q = atomicAdd(&d_cur_an[an_dst[e]], 1);
    d_eid_an[q] = e;
}

__global__ void pack_nodes_kernel(const float* __restrict__ nodes,
                                  const float* __restrict__ state_init) {
    int idx = blockIdx.x * blockDim.x + threadIdx.x;
    if (idx >= NN * 128) return;
    int n = idx >> 7, c = idx & 127;
    float nd = nodes[idx];
    d_SB[(size_t)n * 256 + c]       = state_init[idx];
    d_stateold[idx]                 = 1.0f;
    d_Abase[(size_t)n * 320 + c]    = nd;
    d_SO[(size_t)n * 256 + 128 + c] = nd;
}

__global__ void pack_w_kernel(const float* __restrict__ Ws1) {
    int idx = blockIdx.x * blockDim.x + threadIdx.x;
    if (idx < 256 * 512) {
        int r = idx >> 9, c = idx & 511;
        int sr = (r < 128) ? r : (r + 128);           // state rows / agg_state rows
        d_Wstack[idx] = Ws1[sr * 512 + c];
    } else if (idx < 256 * 512 + 320 * 512) {
        int i2 = idx - 256 * 512;
        int r = i2 >> 9, c = i2 & 511;
        int sr = (r < 128) ? (r + 128) : (r + 256);   // nodes rows / [aggn|agga] rows
        d_Wbase[i2] = Ws1[sr * 512 + c];
    }
}

// ---------------- aggregations ----------------
__global__ void agg_arcs_kernel(const float* __restrict__ arcs,
                                const float* __restrict__ an_vals) {
    int warp = (blockIdx.x * blockDim.x + threadIdx.x) >> 5;
    if (warp >= NN) return;
    int lane = threadIdx.x & 31;
    int p0 = d_off_an[warp], p1 = d_off_an[warp + 1];
    float a0 = 0.f, a1 = 0.f;
    for (int p = p0; p < p1; p++) {
        int e = d_eid_an[p];
        float v = an_vals[e];
        const float* ar = arcs + (size_t)e * 66;
        a0 += v * ar[2 + lane];
        a1 += v * ar[34 + lane];
    }
    d_Abase[(size_t)warp * 320 + 256 + lane] = a0;
    d_Abase[(size_t)warp * 320 + 288 + lane] = a1;
}

// gather SpMM: one warp per destination node; one float4 per lane per source row
__global__ void spmm_kernel(const float4* __restrict__ X4, int xstr4,
                            float4* __restrict__ Y4, int ystr4,
                            const float* __restrict__ vals,
                            const int* __restrict__ src,
                            const int* __restrict__ gate) {
    if (gate && gate[0] == 0) return;
    int warp = (blockIdx.x * blockDim.x + threadIdx.x) >> 5;
    if (warp >= NN) return;
    int lane = threadIdx.x & 31;
    int p0 = d_off_adj[warp], p1 = d_off_adj[warp + 1];
    float4 a = make_float4(0.f, 0.f, 0.f, 0.f);
    for (int p = p0; p < p1; p++) {
        int e = d_eid_adj[p];
        float v = vals[e];
        float4 r = X4[(size_t)src[e] * xstr4 + lane];
        a.x += v * r.x; a.y += v * r.y; a.z += v * r.z; a.w += v * r.w;
    }
    Y4[(size_t)warp * ystr4 + lane] = a;
}

// ---------------- initial convergence check (it=1) ----------------
__global__ void conv_kernel(int it) {
    if (d_cont[it - 1] == 0) return;
    int warp = (blockIdx.x * blockDim.x + threadIdx.x) >> 5;
    if (warp >= NN) return;
    int lane = threadIdx.x & 31;
    float d2 = 0.f, n2 = 0.f;
#pragma unroll
    for (int j = 0; j < 4; j++) {
        float s  = d_SB[(size_t)warp * 256 + lane + 32 * j];
        float so = d_stateold[(size_t)warp * 128 + lane + 32 * j];
        float df = s - so;
        d2 += df * df;
        n2 += so * so;
    }
#pragma unroll
    for (int o = 16; o; o >>= 1) {
        d2 += __shfl_down_sync(0xffffffffu, d2, o);
        n2 += __shfl_down_sync(0xffffffffu, n2, o);
    }
    if (lane == 0 && d2 > THR2 * n2) d_cont[it] = 1;
}

// ---------------- fused state update + next-iteration convergence ----------------
__global__ void update_conv_kernel(int it) {
    if (d_cont[it] == 0) return;
    int warp = (blockIdx.x * blockDim.x + threadIdx.x) >> 5;
    if (warp >= NN) return;
    int lane = threadIdx.x & 31;
    const float4* ns4 = (const float4*)d_NS;
    float4* sb4 = (float4*)d_SB;
    float4* so4 = (float4*)d_stateold;
    float4 nv = ns4[(size_t)warp * 32 + lane];
    float4 ov = sb4[(size_t)warp * 64 + lane];
    so4[(size_t)warp * 32 + lane] = ov;
    sb4[(size_t)warp * 64 + lane] = nv;
    float dx = nv.x - ov.x, dy = nv.y - ov.y, dz = nv.z - ov.z, dw = nv.w - ov.w;
    float d2 = dx * dx + dy * dy + dz * dz + dw * dw;
    float n2 = ov.x * ov.x + ov.y * ov.y + ov.z * ov.z + ov.w * ov.w;
#pragma unroll
    for (int o = 16; o; o >>= 1) {
        d2 += __shfl_xor_sync(0xffffffffu, d2, o);
        n2 += __shfl_xor_sync(0xffffffffu, n2, o);
    }
    if (lane == 0 && d2 > THR2 * n2) d_cont[it + 1] = 1;
}

__global__ void copy_so_kernel() {
    int idx = blockIdx.x * blockDim.x + threadIdx.x;
    if (idx >= NN * 32) return;
    int n = idx >> 5, c = idx & 31;
    ((float4*)d_SO)[(size_t)n * 64 + c] = ((const float4*)d_SB)[(size_t)n * 64 + c];
}

// ---------------- TF32 WMMA GEMM: 4 warps, 64x64 warp tiles ----------------
// C[M x N] = act( A[M x K] @ B[K x N] + Ci ),  ldci==0 => bias broadcast
#define BMg 128
#define BNg 128
#define BKg 16
#define GT  128

template <int ACTF>
__global__ __launch_bounds__(GT) void gemm_tf32(
    const float* __restrict__ A, int lda,
    const float* __restrict__ B, int ldb,
    const float* __restrict__ Ci, int ldci,
    float* __restrict__ C, int ldc,
    int K, const int* __restrict__ gate)
{
    if (gate && gate[0] == 0) return;
    __shared__ float As[2][BMg][BKg + 8];   // row stride 24 floats (96B)
    __shared__ float Bs[2][BKg][BNg + 8];   // row stride 136 floats (544B)

    int tid = threadIdx.x;
    int wid = tid >> 5;
    int wm = wid & 1;        // 2 m-tiles of 64 rows
    int wn = wid >> 1;       // 2 n-tiles of 64 cols
    int m0 = blockIdx.x * BMg;
    int n0 = blockIdx.y * BNg;

    // init accumulators from Ci (matrix if ldci>0, broadcast bias if ldci==0)
    wmma::fragment<wmma::accumulator, 16, 16, 8, float> acc[4][4];
#pragma unroll
    for (int i = 0; i < 4; i++)
#pragma unroll
        for (int j = 0; j < 4; j++)
            wmma::load_matrix_sync(acc[i][j],
                Ci + (size_t)(m0 + wm * 64 + i * 16) * ldci + n0 + wn * 64 + j * 16,
                ldci, wmma::mem_row_major);

    // per-thread load coords (128 threads: 4 float4 each for A and B per stage)
    const float* Ab = A + (size_t)m0 * lda;
    const float* Bb = B + n0;

    // prologue: stage 0
#pragma unroll
    for (int g = 0; g < 4; g++) {
        int idx = tid + g * 128;                 // A: 128 rows x 4 float4
        int r = idx >> 2, cv = (idx & 3) * 4;
        cpa16(&As[0][r][cv], Ab + (size_t)r * lda + cv);
    }
#pragma unroll
    for (int g = 0; g < 4; g++) {
        int idx = tid + g * 128;                 // B: 16 rows x 32 float4
        int r = idx >> 5, cv = (idx & 31) * 4;
        cpa16(&Bs[0][r][cv], Bb + (size_t)r * ldb + cv);
    }
    CP_COMMIT;

    int nst = K / BKg;
    for (int s = 0; s < nst; s++) {
        int cur = s & 1;
        if (s + 1 < nst) {
            int nxt = cur ^ 1;
            int k0 = (s + 1) * BKg;
#pragma unroll
            for (int g = 0; g < 4; g++) {
                int idx = tid + g * 128;
                int r = idx >> 2, cv = (idx & 3) * 4;
                cpa16(&As[nxt][r][cv], Ab + (size_t)r * lda + k0 + cv);
            }
#pragma unroll
            for (int g = 0; g < 4; g++) {
                int idx = tid + g * 128;
                int r = idx >> 5, cv = (idx & 31) * 4;
                cpa16(&Bs[nxt][r][cv], Bb + (size_t)(k0 + r) * ldb + cv);
            }
            CP_COMMIT;
            CP_WAIT1;
        } else {
            CP_WAIT0;
        }
        __syncthreads();
#pragma unroll
        for (int kk = 0; kk < BKg; kk += 8) {
            wmma::fragment<wmma::matrix_a, 16, 16, 8, wmma::precision::tf32, wmma::row_major> af[4];
            wmma::fragment<wmma::matrix_b, 16, 16, 8, wmma::precision::tf32, wmma::row_major> bf[4];
#pragma unroll
            for (int i = 0; i < 4; i++) {
                wmma::load_matrix_sync(af[i], &As[cur][wm * 64 + i * 16][kk], BKg + 8);
#pragma unroll
                for (int e = 0; e < af[i].num_elements; e++)
                    af[i].x[e] = wmma::__float_to_tf32(af[i].x[e]);
            }
#pragma unroll
            for (int j = 0; j < 4; j++) {
                wmma::load_matrix_sync(bf[j], &Bs[cur][kk][wn * 64 + j * 16], BNg + 8);
#pragma unroll
                for (int e = 0; e < bf[j].num_elements; e++)
                    bf[j].x[e] = wmma::__float_to_tf32(bf[j].x[e]);
            }
#pragma unroll
            for (int i = 0; i < 4; i++)
#pragma unroll
                for (int j = 0; j < 4; j++)
                    wmma::mma_sync(acc[i][j], af[i], bf[j], acc[i][j]);
        }
        __syncthreads();
    }

#pragma unroll
    for (int i = 0; i < 4; i++)
#pragma unroll
        for (int j = 0; j < 4; j++) {
            if (ACTF == 1) {
#pragma unroll
                for (int e = 0; e < acc[i][j].num_elements; e++)
                    acc[i][j].x[e] = fast_tanh(acc[i][j].x[e]);
            }
            wmma::store_matrix_sync(
                C + (size_t)(m0 + wm * 64 + i * 16) * ldc + n0 + wn * 64 + j * 16,
                acc[i][j], ldc, wmma::mem_row_major);
        }
}

// ---------------- output head ----------------
__global__ void out_kernel(const float* __restrict__ Wo2, const float* __restrict__ bo2,
                           const int* __restrict__ sm, const int* __restrict__ om,
                           float* __restrict__ out) {
    __shared__ float w[512 * 7];
    __shared__ float b[7];
    for (int i = threadIdx.x; i < 512 * 7; i += blockDim.x) w[i] = Wo2[i];
    if (threadIdx.x < 7) b[threadIdx.x] = bo2[threadIdx.x];
    __syncthreads();
    int warp = (blockIdx.x * blockDim.x + threadIdx.x) >> 5;
    if (warp >= NN) return;
    int lane = threadIdx.x & 31;
    float acc[7] = {0, 0, 0, 0, 0, 0, 0};
    const float* h = d_H2 + (size_t)warp * 512;
    for (int k = lane; k < 512; k += 32) {
        float hv = h[k];
#pragma unroll
        for (int j = 0; j < 7; j++) acc[j] += hv * w[k * 7 + j];
    }
#pragma unroll
    for (int j = 0; j < 7; j++)
#pragma unroll
        for (int o = 16; o; o >>= 1)
            acc[j] += __shfl_down_sync(0xffffffffu, acc[j], o);
    if (lane == 0) {
        float m = (sm[warp] != 0 && om[warp] != 0) ? 1.0f : 0.0f;
#pragma unroll
        for (int j = 0; j < 7; j++) out[(size_t)warp * 7 + j] = (acc[j] + b[j]) * m;
    }
}

// ---------------- host launch ----------------
extern "C" void kernel_launch(void* const* d_in, const int* in_sizes, int n_in,
                              void* d_out, int out_size) {
    const float* nodes      = (const float*)d_in[0];
    const float* arcs       = (const float*)d_in[1];
    const int* set_mask     = (const int*)d_in[2];     // bool stored as int32
    const int* out_mask     = (const int*)d_in[3];
    const int* adj_src      = (const int*)d_in[4];
    const int* adj_dst      = (const int*)d_in[5];
    const float* adj_vals   = (const float*)d_in[6];
    const int* an_dst       = (const int*)d_in[7];
    const float* an_vals    = (const float*)d_in[8];
    const float* state_init = (const float*)d_in[9];
    const float* Ws1        = (const float*)d_in[10];
    const float* bs1        = (const float*)d_in[11];
    const float* Ws2        = (const float*)d_in[12];
    const float* bs2        = (const float*)d_in[13];
    const float* Wo1        = (const float*)d_in[14];
    const float* bo1        = (const float*)d_in[15];
    const float* Wo2        = (const float*)d_in[16];
    const float* bo2        = (const float*)d_in[17];
    float* out              = (float*)d_out;

    float *pSB, *pSO, *pAbase, *pBbase, *pH, *pNS, *pH2, *pWstack, *pWbase;
    int* pcont;
    cudaGetSymbolAddress((void**)&pSB, d_SB);
    cudaGetSymbolAddress((void**)&pSO, d_SO);
    cudaGetSymbolAddress((void**)&pAbase, d_Abase);
    cudaGetSymbolAddress((void**)&pBbase, d_Bbase);
    cudaGetSymbolAddress((void**)&pH, d_H);
    cudaGetSymbolAddress((void**)&pNS, d_NS);
    cudaGetSymbolAddress((void**)&pH2, d_H2);
    cudaGetSymbolAddress((void**)&pWstack, d_Wstack);
    cudaGetSymbolAddress((void**)&pWbase, d_Wbase);
    cudaGetSymbolAddress((void**)&pcont, d_cont);

    const int T = 256;
    // setup + CSR build
    setup_kernel<<<(2 * NN + T - 1) / T, T>>>();
    count_kernel<<<(EE + T - 1) / T, T>>>(adj_dst, an_dst);
    scan_kernel<<<2, 1024>>>();
    scatter_kernel<<<(EE + T - 1) / T, T>>>(adj_dst, an_dst);

    pack_nodes_kernel<<<(NN * 128 + T - 1) / T, T>>>(nodes, state_init);
    pack_w_kernel<<<(256 * 512 + 320 * 512 + T - 1) / T, T>>>(Ws1);

    int warpBlocks = (NN * 32 + T - 1) / T;
    agg_arcs_kernel<<<warpBlocks, T>>>(arcs, an_vals);
    // agg_nodes -> Abase cols 128:256 (nodes row = 32 float4, Abase row = 80 float4)
    spmm_kernel<<<warpBlocks, T>>>((const float4*)nodes, 32,
                                   ((float4*)pAbase) + 32, 80, adj_vals, adj_src, nullptr);

    // Bbase = Abase @ Wbase + bs1  (no act)
    gemm_tf32<0><<<dim3(NPAD / BMg, 512 / BNg), GT>>>(
        pAbase, 320, pWbase, 512, bs1, 0, pBbase, 512, 320, nullptr);

    conv_kernel<<<warpBlocks, T>>>(1);

    for (int it = 1; it <= MAX_IT; it++) {
        // agg_states -> SB cols 128:256 (SB row = 64 float4)
        spmm_kernel<<<warpBlocks, T>>>((const float4*)pSB, 64,
                                       ((float4*)pSB) + 32, 64, adj_vals, adj_src, pcont + it);
        // H = tanh(SB @ Wstack + Bbase)
        gemm_tf32<1><<<dim3(NPAD / BMg, 512 / BNg), GT>>>(
            pSB, 256, pWstack, 512, pBbase, 512, pH, 512, 256, pcont + it);
        // NS = tanh(H @ Ws2 + bs2)
        gemm_tf32<1><<<dim3(NPAD / BMg, 128 / BNg), GT>>>(
            pH, 512, Ws2, 128, bs2, 0, pNS, 128, 512, pcont + it);
        // state <- NS, stateold <- state, cont[it+1] from (new,old)
        update_conv_kernel<<<warpBlocks, T>>>(it);
    }

    copy_so_kernel<<<(NN * 32 + T - 1) / T, T>>>();
    // H2 = tanh(SO @ Wo1 + bo1)
    gemm_tf32<1><<<dim3(NPAD / BMg, 512 / BNg), GT>>>(
        pSO, 256, Wo1, 512, bo1, 0, pH2, 512, 256, nullptr);
    out_kernel<<<warpBlocks, T>>>(Wo2, bo2, set_mask, out_mask, out);
}